// round 1
// baseline (speedup 1.0000x reference)
#include <cuda_runtime.h>
#include <cuda_bf16.h>
#include <cstdint>

// S4 adaptive embedding: 4 buckets, cutoffs [0,20000,40000,200000,267735]
// d_i = 1024, 256, 64, 16 ; D_PROJ = 1024 ; scale = sqrt(1024) = 32
//
// Pipeline (all graph-capturable, no allocations):
//   1) reset_detect: zero bucket counters + detect int64-vs-int32 id layout
//   2) bucketize: scatter token positions + local emb indices per bucket
//   3) 4x bucket_gemm<D>: tiled fp32 NT-GEMM  out[t, :] = emb_row @ proj^T * 32

#define NTOK 16384
#define DPROJ 1024

__device__ int g_cnt[4];
__device__ int g_tok[4][NTOK];
__device__ int g_idx[4][NTOK];
__device__ int g_is64;

__global__ void reset_detect_kernel(const void* ids_raw) {
    int t = threadIdx.x;
    if (t < 4) g_cnt[t] = 0;
    // Detect layout: if ids are int64 (little-endian, values < 2^31), every odd
    // 32-bit word is zero. If int32, odd words are random ids (~0 chance all zero).
    // We only read the first 2048 int32 words (8KB) — in-bounds for both layouts.
    const int* w = (const int*)ids_raw;
    int nz = 0;
    for (int i = t; i < 1024; i += 256) nz |= w[2 * i + 1];
    int any = __syncthreads_or(nz);
    if (t == 0) g_is64 = (any == 0) ? 1 : 0;
}

__global__ void bucketize_kernel(const void* ids_raw) {
    int i = blockIdx.x * blockDim.x + threadIdx.x;
    if (i >= NTOK) return;
    long long id;
    if (g_is64) id = ((const long long*)ids_raw)[i];
    else        id = (long long)((const int*)ids_raw)[i];
    int b, l;
    if (id < 20000)       { b = 0; l = 0; }
    else if (id < 40000)  { b = 1; l = 20000; }
    else if (id < 200000) { b = 2; l = 40000; }
    else                  { b = 3; l = 200000; }
    int slot = atomicAdd(&g_cnt[b], 1);
    g_tok[b][slot] = i;
    g_idx[b][slot] = (int)(id - l);
}

// Tiled NT-GEMM: C[64 tokens][64 dims] per block, K = D (templated).
// A = gathered emb rows [64, D], B = proj rows [64, D], C = A @ B^T * 32.
template <int D>
__global__ void __launch_bounds__(256) bucket_gemm_kernel(
    const float* __restrict__ emb,
    const float* __restrict__ proj,
    float* __restrict__ out,
    int bucket)
{
    constexpr int KC = (D < 32) ? D : 32;
    const int n = g_cnt[bucket];
    const int m0 = blockIdx.x * 64;
    if (m0 >= n) return;
    const int n0 = blockIdx.y * 64;

    __shared__ float As[KC][68];   // transposed: As[k][m], padded to 68 (16B-aligned rows, bank-spread)
    __shared__ float Bs[KC][68];   // transposed: Bs[k][nn]
    __shared__ int s_tok[64];
    __shared__ int s_idx[64];

    const int tid = threadIdx.x;
    if (tid < 64) {
        int m = m0 + tid;
        if (m < n) { s_tok[tid] = g_tok[bucket][m]; s_idx[tid] = g_idx[bucket][m]; }
        else       { s_tok[tid] = -1;               s_idx[tid] = 0; }
    }
    __syncthreads();

    float acc[4][4] = {};
    const int ty = tid >> 4;       // 0..15 -> token group (4 tokens)
    const int tx = tid & 15;       // 0..15 -> dim group (4 dims)

    constexpr int F4_PER_ROW = KC / 4;        // 8 (KC=32) or 4 (KC=16)
    constexpr int TOTAL_F4   = 64 * F4_PER_ROW;

    for (int k0 = 0; k0 < D; k0 += KC) {
        // Load A tile (gathered emb rows), store transposed into smem
        #pragma unroll
        for (int f = tid; f < TOTAL_F4; f += 256) {
            int m  = f / F4_PER_ROW;
            int kq = f % F4_PER_ROW;
            float4 v;
            if (s_tok[m] >= 0)
                v = *(const float4*)&emb[(size_t)s_idx[m] * D + k0 + kq * 4];
            else
                v = make_float4(0.f, 0.f, 0.f, 0.f);
            As[kq * 4 + 0][m] = v.x;
            As[kq * 4 + 1][m] = v.y;
            As[kq * 4 + 2][m] = v.z;
            As[kq * 4 + 3][m] = v.w;
        }
        // Load B tile (proj rows [n0+nn][k0..k0+KC)), store transposed
        #pragma unroll
        for (int f = tid; f < TOTAL_F4; f += 256) {
            int nn = f / F4_PER_ROW;
            int kq = f % F4_PER_ROW;
            float4 v = *(const float4*)&proj[(size_t)(n0 + nn) * D + k0 + kq * 4];
            Bs[kq * 4 + 0][nn] = v.x;
            Bs[kq * 4 + 1][nn] = v.y;
            Bs[kq * 4 + 2][nn] = v.z;
            Bs[kq * 4 + 3][nn] = v.w;
        }
        __syncthreads();

        #pragma unroll
        for (int k = 0; k < KC; k++) {
            float a[4], b[4];
            *(float4*)a = *(const float4*)&As[k][ty * 4];
            *(float4*)b = *(const float4*)&Bs[k][tx * 4];
            #pragma unroll
            for (int i = 0; i < 4; i++)
                #pragma unroll
                for (int j = 0; j < 4; j++)
                    acc[i][j] += a[i] * b[j];
        }
        __syncthreads();
    }

    // Epilogue: scatter rows to out[token][n0 + tx*4 .. +3], fused *32 scale
    #pragma unroll
    for (int i = 0; i < 4; i++) {
        int m   = ty * 4 + i;
        int tok = s_tok[m];
        if (tok >= 0) {
            float4 v = make_float4(acc[i][0] * 32.f, acc[i][1] * 32.f,
                                   acc[i][2] * 32.f, acc[i][3] * 32.f);
            *(float4*)&out[(size_t)tok * DPROJ + n0 + tx * 4] = v;
        }
    }
}

extern "C" void kernel_launch(void* const* d_in, const int* in_sizes, int n_in,
                              void* d_out, int out_size) {
    const void*  ids   = d_in[0];
    const float* emb0  = (const float*)d_in[1];
    const float* proj0 = (const float*)d_in[2];
    const float* emb1  = (const float*)d_in[3];
    const float* proj1 = (const float*)d_in[4];
    const float* emb2  = (const float*)d_in[5];
    const float* proj2 = (const float*)d_in[6];
    const float* emb3  = (const float*)d_in[7];
    const float* proj3 = (const float*)d_in[8];
    float* out = (float*)d_out;

    reset_detect_kernel<<<1, 256>>>(ids);
    bucketize_kernel<<<NTOK / 256, 256>>>(ids);

    dim3 grid(NTOK / 64, DPROJ / 64);   // 256 x 16 ; blocks past the bucket count exit early
    bucket_gemm_kernel<1024><<<grid, 256>>>(emb0, proj0, out, 0);
    bucket_gemm_kernel<256 ><<<grid, 256>>>(emb1, proj1, out, 1);
    bucket_gemm_kernel<64  ><<<grid, 256>>>(emb2, proj2, out, 2);
    bucket_gemm_kernel<16  ><<<grid, 256>>>(emb3, proj3, out, 3);
}